// round 5
// baseline (speedup 1.0000x reference)
#include <cuda_runtime.h>

// Inverse 2D DWT, single level. (4,64,256,256) f32 x4 subbands -> (4,64,512,512) f32.
// Warp-autonomous: one warp owns a 64-col strip x RW rows; each lane owns 2 adjacent
// columns (one f32x2 per subband-row). Rolling 3-row window, each element loaded once,
// next row's loads software-pipelined under the row pass. Cross-strip halo: each lane
// keeps one scalar halo column per subband, packed pairwise (s,d) so the halo column
// pass reuses the packed f32x2 coefficients. No smem, no barriers.

#define HH 256
#define WW 256
#define RW 32
#define NT 128

typedef unsigned long long u64;

__device__ __forceinline__ u64 pk(float lo, float hi) {
    u64 r; asm("mov.b64 %0, {%1, %2};" : "=l"(r) : "f"(lo), "f"(hi)); return r;
}
__device__ __forceinline__ void unpk(u64 v, float& lo, float& hi) {
    asm("mov.b64 {%0, %1}, %2;" : "=f"(lo), "=f"(hi) : "l"(v));
}
__device__ __forceinline__ float lof(u64 v) { float a, b; unpk(v, a, b); return a; }
__device__ __forceinline__ float hif(u64 v) { float a, b; unpk(v, a, b); return b; }
__device__ __forceinline__ u64 ffma2(u64 a, u64 b, u64 c) {
    u64 d; asm("fma.rn.f32x2 %0, %1, %2, %3;" : "=l"(d) : "l"(a), "l"(b), "l"(c)); return d;
}
__device__ __forceinline__ u64 fmul2(u64 a, u64 b) {
    u64 d; asm("mul.rn.f32x2 %0, %1, %2;" : "=l"(d) : "l"(a), "l"(b)); return d;
}
__device__ __forceinline__ int reflH(int i) {
    return i < 0 ? -i : (i >= HH ? 2 * HH - 2 - i : i);
}
__device__ __forceinline__ float shup(float v) { return __shfl_up_sync(0xffffffffu, v, 1); }
__device__ __forceinline__ float shdn(float v) { return __shfl_down_sync(0xffffffffu, v, 1); }
__device__ __forceinline__ u64 ldg2(const float* __restrict__ p, int row) {
    return *(const u64*)(p + (size_t)row * WW);
}

__global__ __launch_bounds__(NT, 6)
void idwt2d(const float* __restrict__ ss, const float* __restrict__ sd,
            const float* __restrict__ ds, const float* __restrict__ dd,
            const float* __restrict__ hf, const float* __restrict__ gf,
            float* __restrict__ out)
{
    const int lane = threadIdx.x & 31;
    const int wid  = threadIdx.x >> 5;     // strip index 0..3
    const int bc   = blockIdx.z;
    const int r0   = blockIdx.y * RW;
    const int wb   = 64 * wid;
    const int c    = wb + 2 * lane;

    // halo column: lanes 0-30 -> reflW(wb-1) (broadcast), lane 31 -> reflW(wb+64)
    const int hcol = (lane == 31) ? ((wb + 64 < WW) ? wb + 64 : WW - 2)
                                  : ((wb > 0) ? wb - 1 : 1);
    const int dq = hcol - c;   // halo offset relative to owned base pointers

    const size_t base = (size_t)bc * (HH * WW);
    const float* __restrict__ pss = ss + base + c;
    const float* __restrict__ psd = sd + base + c;
    const float* __restrict__ pds = ds + base + c;
    const float* __restrict__ pdd = dd + base + c;
    float* __restrict__ pout = out + (size_t)bc * (4 * HH * WW) + 2 * c;

    // packed filter coefficients only (scalars die after packing)
    u64 H0, H1, H2, H3, H4, H5, G0, G1, G2, G3, G4, G5;
    {
        const float a0 = hf[0], a1 = hf[1], a2 = hf[2], a3 = hf[3], a4 = hf[4], a5 = hf[5];
        const float b0 = gf[0], b1 = gf[1], b2 = gf[2], b3 = gf[3], b4 = gf[4], b5 = gf[5];
        H0 = pk(a0, a0); H1 = pk(a1, a1); H2 = pk(a2, a2);
        H3 = pk(a3, a3); H4 = pk(a4, a4); H5 = pk(a5, a5);
        G0 = pk(b0, b0); G1 = pk(b1, b1); G2 = pk(b2, b2);
        G3 = pk(b3, b3); G4 = pk(b4, b4); G5 = pk(b5, b5);
    }

    // prime 3-row window (rows r0-1, r0, r0+1); halo packed: P=(ss,ds), Q=(sd,dd)
    const int rm = reflH(r0 - 1);
    const int rp = reflH(r0 + 1);
    u64 S0 = ldg2(pss, rm), T0 = ldg2(psd, rm), U0 = ldg2(pds, rm), V0 = ldg2(pdd, rm);
    u64 S1 = ldg2(pss, r0), T1 = ldg2(psd, r0), U1 = ldg2(pds, r0), V1 = ldg2(pdd, r0);
    u64 S2 = ldg2(pss, rp), T2 = ldg2(psd, rp), U2 = ldg2(pds, rp), V2 = ldg2(pdd, rp);
    u64 P0 = pk(pss[(size_t)rm * WW + dq], pds[(size_t)rm * WW + dq]);
    u64 Q0 = pk(psd[(size_t)rm * WW + dq], pdd[(size_t)rm * WW + dq]);
    u64 P1 = pk(pss[(size_t)r0 * WW + dq], pds[(size_t)r0 * WW + dq]);
    u64 Q1 = pk(psd[(size_t)r0 * WW + dq], pdd[(size_t)r0 * WW + dq]);
    u64 P2 = pk(pss[(size_t)rp * WW + dq], pds[(size_t)rp * WW + dq]);
    u64 Q2 = pk(psd[(size_t)rp * WW + dq], pdd[(size_t)rp * WW + dq]);

    #pragma unroll 4
    for (int i = 0; i < RW; ++i) {
        const int r = r0 + i;

        // ---- column pass (f32x2, both owned columns) ----
        const u64 A0 = ffma2(H4, S0, ffma2(H2, S1, ffma2(H0, S2,
                       ffma2(G4, T0, ffma2(G2, T1, fmul2(G0, T2))))));
        const u64 A1 = ffma2(H5, S0, ffma2(H3, S1, ffma2(H1, S2,
                       ffma2(G5, T0, ffma2(G3, T1, fmul2(G1, T2))))));
        const u64 A2 = ffma2(H4, U0, ffma2(H2, U1, ffma2(H0, U2,
                       ffma2(G4, V0, ffma2(G2, V1, fmul2(G0, V2))))));
        const u64 A3 = ffma2(H5, U0, ffma2(H3, U1, ffma2(H1, U2,
                       ffma2(G5, V0, ffma2(G3, V1, fmul2(G1, V2))))));

        // ---- halo column pass (packed: lo = s-side, hi = d-side) ----
        const u64 B02 = ffma2(H4, P0, ffma2(H2, P1, ffma2(H0, P2,
                        ffma2(G4, Q0, ffma2(G2, Q1, fmul2(G0, Q2))))));  // (b0, b2)
        const u64 B13 = ffma2(H5, P0, ffma2(H3, P1, ffma2(H1, P2,
                        ffma2(G5, Q0, ffma2(G3, Q1, fmul2(G1, Q2))))));  // (b1, b3)

        // ---- roll window + issue next row's loads (hidden under row pass) ----
        S0 = S1; S1 = S2; T0 = T1; T1 = T2;
        U0 = U1; U1 = U2; V0 = V1; V1 = V2;
        P0 = P1; P1 = P2; Q0 = Q1; Q1 = Q2;
        const int rn = reflH(r + 2);
        S2 = ldg2(pss, rn); T2 = ldg2(psd, rn);
        U2 = ldg2(pds, rn); V2 = ldg2(pdd, rn);
        P2 = pk(pss[(size_t)rn * WW + dq], pds[(size_t)rn * WW + dq]);
        Q2 = pk(psd[(size_t)rn * WW + dq], pdd[(size_t)rn * WW + dq]);

        // ---- row pass: py=0 uses (A0,A2, b0,b2); py=1 uses (A1,A3, b1,b3) ----
        #pragma unroll
        for (int py = 0; py < 2; ++py) {
            const u64 X = py ? A1 : A0;
            const u64 Y = py ? A3 : A2;
            const u64 B = py ? B13 : B02;
            const float hx = lof(B);   // halo of s-side
            const float hy = hif(B);   // halo of d-side

            float xm = shup(hif(X)); if (lane == 0)  xm = hx;   // v[c-1]
            float xp = shdn(lof(X)); if (lane == 31) xp = hx;   // v[c+2]
            float ym = shup(hif(Y)); if (lane == 0)  ym = hy;
            float yp = shdn(lof(Y)); if (lane == 31) yp = hy;

            const u64 AX = pk(xm, lof(X)), CX = pk(hif(X), xp);
            const u64 AY = pk(ym, lof(Y)), CY = pk(hif(Y), yp);

            const u64 pe = ffma2(H4, AX, ffma2(H2, X, ffma2(H0, CX,
                           ffma2(G4, AY, ffma2(G2, Y, fmul2(G0, CY))))));
            const u64 po = ffma2(H5, AX, ffma2(H3, X, ffma2(H1, CX,
                           ffma2(G5, AY, ffma2(G3, Y, fmul2(G1, CY))))));

            float e0, e1, f0, f1;
            unpk(pe, e0, e1); unpk(po, f0, f1);
            *(float4*)(pout + (size_t)(2 * r + py) * (2 * WW)) = make_float4(e0, f0, e1, f1);
        }
    }
}

extern "C" void kernel_launch(void* const* d_in, const int* in_sizes, int n_in,
                              void* d_out, int out_size) {
    const float* ss = (const float*)d_in[0];
    const float* sd = (const float*)d_in[1];
    const float* ds = (const float*)d_in[2];
    const float* dd = (const float*)d_in[3];
    const float* h  = (const float*)d_in[4];
    const float* g  = (const float*)d_in[5];
    float* out = (float*)d_out;

    dim3 grid(1, HH / RW, 4 * 64);   // (1, 8, 256) = 2048 blocks x 4 warps
    idwt2d<<<grid, NT>>>(ss, sd, ds, dd, h, g, out);
}

// round 6
// speedup vs baseline: 1.1963x; 1.1963x over previous
#include <cuda_runtime.h>

// Inverse 2D DWT, single level. (4,64,256,256) f32 x4 subbands -> (4,64,512,512) f32.
// Warp-autonomous: one warp owns a 64-col strip x RW rows; each lane owns 2 adjacent
// columns. Processes 2 rows per iteration with ALL loads for the NEXT iteration
// front-batched (prefetch distance = 1 full iteration, ~150 instrs of cover).
// Halo columns kept as scalar floats through the pipeline (no early pack-wait);
// packed into f32x2 only at use. Streaming cache hints on touch-once data.
// No smem, no barriers.

#define HH 256
#define WW 256
#define RW 32
#define NT 128

typedef unsigned long long u64;

__device__ __forceinline__ u64 pk(float lo, float hi) {
    u64 r; asm("mov.b64 %0, {%1, %2};" : "=l"(r) : "f"(lo), "f"(hi)); return r;
}
__device__ __forceinline__ void unpk(u64 v, float& lo, float& hi) {
    asm("mov.b64 {%0, %1}, %2;" : "=f"(lo), "=f"(hi) : "l"(v));
}
__device__ __forceinline__ float lof(u64 v) { float a, b; unpk(v, a, b); return a; }
__device__ __forceinline__ float hif(u64 v) { float a, b; unpk(v, a, b); return b; }
__device__ __forceinline__ u64 ffma2(u64 a, u64 b, u64 c) {
    u64 d; asm("fma.rn.f32x2 %0, %1, %2, %3;" : "=l"(d) : "l"(a), "l"(b), "l"(c)); return d;
}
__device__ __forceinline__ u64 fmul2(u64 a, u64 b) {
    u64 d; asm("mul.rn.f32x2 %0, %1, %2;" : "=l"(d) : "l"(a), "l"(b)); return d;
}
__device__ __forceinline__ int reflH(int i) {
    return i < 0 ? -i : (i >= HH ? 2 * HH - 2 - i : i);
}
__device__ __forceinline__ float shup(float v) { return __shfl_up_sync(0xffffffffu, v, 1); }
__device__ __forceinline__ float shdn(float v) { return __shfl_down_sync(0xffffffffu, v, 1); }
__device__ __forceinline__ u64 ldg2(const float* __restrict__ p, int row) {
    return __ldcs((const unsigned long long*)(p + (size_t)row * WW));
}
__device__ __forceinline__ float ldg1(const float* __restrict__ p, int row, int dq) {
    return __ldcs(p + (size_t)row * WW + dq);
}

__global__ __launch_bounds__(NT, 4)
void idwt2d(const float* __restrict__ ss, const float* __restrict__ sd,
            const float* __restrict__ ds, const float* __restrict__ dd,
            const float* __restrict__ hf, const float* __restrict__ gf,
            float* __restrict__ out)
{
    const int lane = threadIdx.x & 31;
    const int wid  = threadIdx.x >> 5;     // strip index 0..3
    const int bc   = blockIdx.z;
    const int r0   = blockIdx.y * RW;
    const int wb   = 64 * wid;
    const int c    = wb + 2 * lane;

    // halo column (W-reflection built in): lanes 0-30 -> col wb-1 (broadcast), lane 31 -> col wb+64
    const int hcol = (lane == 31) ? ((wb + 64 < WW) ? wb + 64 : WW - 2)
                                  : ((wb > 0) ? wb - 1 : 1);
    const int dq = hcol - c;

    const size_t base = (size_t)bc * (HH * WW);
    const float* __restrict__ pss = ss + base + c;
    const float* __restrict__ psd = sd + base + c;
    const float* __restrict__ pds = ds + base + c;
    const float* __restrict__ pdd = dd + base + c;
    float* __restrict__ pout = out + (size_t)bc * (4 * HH * WW) + 2 * c;

    u64 H0, H1, H2, H3, H4, H5, G0, G1, G2, G3, G4, G5;
    {
        const float a0 = hf[0], a1 = hf[1], a2 = hf[2], a3 = hf[3], a4 = hf[4], a5 = hf[5];
        const float b0 = gf[0], b1 = gf[1], b2 = gf[2], b3 = gf[3], b4 = gf[4], b5 = gf[5];
        H0 = pk(a0, a0); H1 = pk(a1, a1); H2 = pk(a2, a2);
        H3 = pk(a3, a3); H4 = pk(a4, a4); H5 = pk(a5, a5);
        G0 = pk(b0, b0); G1 = pk(b1, b1); G2 = pk(b2, b2);
        G3 = pk(b3, b3); G4 = pk(b4, b4); G5 = pk(b5, b5);
    }

    // window: rows r-1, r, r+1, r+2 (owned as f32x2; halo as scalars)
    u64 WS[4], WT[4], WU[4], WV[4];
    float HS[4], HT[4], HU[4], HV[4];
    {
        const int rows[4] = { reflH(r0 - 1), r0, r0 + 1, r0 + 2 };
        #pragma unroll
        for (int k = 0; k < 4; ++k) {
            const int rr = rows[k];
            WS[k] = ldg2(pss, rr); WT[k] = ldg2(psd, rr);
            WU[k] = ldg2(pds, rr); WV[k] = ldg2(pdd, rr);
            HS[k] = ldg1(pss, rr, dq); HT[k] = ldg1(psd, rr, dq);
            HU[k] = ldg1(pds, rr, dq); HV[k] = ldg1(pdd, rr, dq);
        }
    }

    #pragma unroll 2
    for (int i = 0; i < RW; i += 2) {
        const int r = r0 + i;

        // ---- front-batched prefetch for NEXT iteration (rows r+3, r+4) ----
        const int ra = reflH(r + 3), rb = reflH(r + 4);
        const u64 PS0 = ldg2(pss, ra), PT0 = ldg2(psd, ra);
        const u64 PU0 = ldg2(pds, ra), PV0 = ldg2(pdd, ra);
        const u64 PS1 = ldg2(pss, rb), PT1 = ldg2(psd, rb);
        const u64 PU1 = ldg2(pds, rb), PV1 = ldg2(pdd, rb);
        const float hsA = ldg1(pss, ra, dq), htA = ldg1(psd, ra, dq);
        const float huA = ldg1(pds, ra, dq), hvA = ldg1(pdd, ra, dq);
        const float hsB = ldg1(pss, rb, dq), htB = ldg1(psd, rb, dq);
        const float huB = ldg1(pds, rb, dq), hvB = ldg1(pdd, rb, dq);

        // ---- compute the 2 owned rows from the current window ----
        #pragma unroll
        for (int k = 0; k < 2; ++k) {
            // column pass (f32x2, both owned columns)
            const u64 A0 = ffma2(H4, WS[k], ffma2(H2, WS[k+1], ffma2(H0, WS[k+2],
                           ffma2(G4, WT[k], ffma2(G2, WT[k+1], fmul2(G0, WT[k+2]))))));
            const u64 A1 = ffma2(H5, WS[k], ffma2(H3, WS[k+1], ffma2(H1, WS[k+2],
                           ffma2(G5, WT[k], ffma2(G3, WT[k+1], fmul2(G1, WT[k+2]))))));
            const u64 A2 = ffma2(H4, WU[k], ffma2(H2, WU[k+1], ffma2(H0, WU[k+2],
                           ffma2(G4, WV[k], ffma2(G2, WV[k+1], fmul2(G0, WV[k+2]))))));
            const u64 A3 = ffma2(H5, WU[k], ffma2(H3, WU[k+1], ffma2(H1, WU[k+2],
                           ffma2(G5, WV[k], ffma2(G3, WV[k+1], fmul2(G1, WV[k+2]))))));

            // halo column pass: pack at use (lo = s-side, hi = d-side)
            const u64 P0 = pk(HS[k],   HU[k]),   Q0 = pk(HT[k],   HV[k]);
            const u64 P1 = pk(HS[k+1], HU[k+1]), Q1 = pk(HT[k+1], HV[k+1]);
            const u64 P2 = pk(HS[k+2], HU[k+2]), Q2 = pk(HT[k+2], HV[k+2]);
            const u64 B02 = ffma2(H4, P0, ffma2(H2, P1, ffma2(H0, P2,
                            ffma2(G4, Q0, ffma2(G2, Q1, fmul2(G0, Q2))))));  // (b0,b2)
            const u64 B13 = ffma2(H5, P0, ffma2(H3, P1, ffma2(H1, P2,
                            ffma2(G5, Q0, ffma2(G3, Q1, fmul2(G1, Q2))))));  // (b1,b3)

            // row pass
            #pragma unroll
            for (int py = 0; py < 2; ++py) {
                const u64 X = py ? A1 : A0;
                const u64 Y = py ? A3 : A2;
                const u64 B = py ? B13 : B02;
                const float hx = lof(B), hy = hif(B);

                float xm = shup(hif(X)); if (lane == 0)  xm = hx;   // v[c-1]
                float xp = shdn(lof(X)); if (lane == 31) xp = hx;   // v[c+2]
                float ym = shup(hif(Y)); if (lane == 0)  ym = hy;
                float yp = shdn(lof(Y)); if (lane == 31) yp = hy;

                const u64 AX = pk(xm, lof(X)), CX = pk(hif(X), xp);
                const u64 AY = pk(ym, lof(Y)), CY = pk(hif(Y), yp);

                const u64 pe = ffma2(H4, AX, ffma2(H2, X, ffma2(H0, CX,
                               ffma2(G4, AY, ffma2(G2, Y, fmul2(G0, CY))))));
                const u64 po = ffma2(H5, AX, ffma2(H3, X, ffma2(H1, CX,
                               ffma2(G5, AY, ffma2(G3, Y, fmul2(G1, CY))))));

                float e0, e1, f0, f1;
                unpk(pe, e0, e1); unpk(po, f0, f1);
                __stcs((float4*)(pout + (size_t)(2 * (r + k) + py) * (2 * WW)),
                       make_float4(e0, f0, e1, f1));
            }
        }

        // ---- roll window by 2 rows; prefetched data lands in slots 2,3 ----
        WS[0] = WS[2]; WS[1] = WS[3]; WS[2] = PS0; WS[3] = PS1;
        WT[0] = WT[2]; WT[1] = WT[3]; WT[2] = PT0; WT[3] = PT1;
        WU[0] = WU[2]; WU[1] = WU[3]; WU[2] = PU0; WU[3] = PU1;
        WV[0] = WV[2]; WV[1] = WV[3]; WV[2] = PV0; WV[3] = PV1;
        HS[0] = HS[2]; HS[1] = HS[3]; HS[2] = hsA; HS[3] = hsB;
        HT[0] = HT[2]; HT[1] = HT[3]; HT[2] = htA; HT[3] = htB;
        HU[0] = HU[2]; HU[1] = HU[3]; HU[2] = huA; HU[3] = huB;
        HV[0] = HV[2]; HV[1] = HV[3]; HV[2] = hvA; HV[3] = hvB;
    }
}

extern "C" void kernel_launch(void* const* d_in, const int* in_sizes, int n_in,
                              void* d_out, int out_size) {
    const float* ss = (const float*)d_in[0];
    const float* sd = (const float*)d_in[1];
    const float* ds = (const float*)d_in[2];
    const float* dd = (const float*)d_in[3];
    const float* h  = (const float*)d_in[4];
    const float* g  = (const float*)d_in[5];
    float* out = (float*)d_out;

    dim3 grid(1, HH / RW, 4 * 64);   // (1, 8, 256) = 2048 blocks x 4 warps
    idwt2d<<<grid, NT>>>(ss, sd, ds, dd, h, g, out);
}